// round 2
// baseline (speedup 1.0000x reference)
#include <cuda_runtime.h>

#define B   16
#define KV  8192
#define D   1024
#define D4  256        // D / 4 (float4 count per row)
#define SS  8224       // score stride per batch (>= KV+1, padded)
#define NSPLIT 64      // k-splits in the A*V kernel

// ---------------- device scratch (no allocations allowed) ----------------
__device__ float g_q [B * D];
__device__ float g_nk[B * D];
__device__ float g_nv[B * D];
__device__ float g_scores[B * SS];                 // scores, then softmax weights in place
__device__ float g_partial[B * NSPLIT * D];        // partial outputs per k-split (4 MB)

// ---------------- K0: projections q/new_k/new_v = x @ W^T ----------------
// grid (384, 2), block 256. 8 warps/block, 1 output row each, 8 batches per block.
__global__ void proj_kernel(const float* __restrict__ x,
                            const float* __restrict__ wq,
                            const float* __restrict__ wk,
                            const float* __restrict__ wv) {
    __shared__ float4 xs[8 * D4];   // 8 batches of x, 32 KB
    const int tid  = threadIdx.x;
    const int warp = tid >> 5;
    const int lane = tid & 31;
    const int grp  = blockIdx.y;    // batch group (0 or 1)

    const float4* x4 = (const float4*)x;
    for (int i = tid; i < 8 * D4; i += 256) xs[i] = x4[grp * 8 * D4 + i];
    __syncthreads();

    const int row = blockIdx.x * 8 + warp;   // 0..3071
    const int mat = row >> 10;
    const int e   = row & 1023;
    const float* W  = (mat == 0) ? wq  : (mat == 1) ? wk  : wv;
    float*      out = (mat == 0) ? g_q : (mat == 1) ? g_nk : g_nv;
    const float4* W4 = (const float4*)W;

    float acc[8];
#pragma unroll
    for (int b = 0; b < 8; b++) acc[b] = 0.f;

#pragma unroll
    for (int ii = 0; ii < 8; ii++) {
        const int i = lane + ii * 32;
        const float4 w4 = W4[e * D4 + i];
#pragma unroll
        for (int b = 0; b < 8; b++) {
            const float4 xv = xs[b * D4 + i];
            acc[b] += w4.x * xv.x + w4.y * xv.y + w4.z * xv.z + w4.w * xv.w;
        }
    }
#pragma unroll
    for (int b = 0; b < 8; b++) {
#pragma unroll
        for (int o = 16; o > 0; o >>= 1)
            acc[b] += __shfl_xor_sync(0xffffffffu, acc[b], o);
    }
    if (lane == 0) {
#pragma unroll
        for (int b = 0; b < 8; b++)
            out[(grp * 8 + b) * D + e] = acc[b];
    }
}

// ---------------- K1: scores[b][k] = q[b] . cache_k[b][k] / sqrt(D) ----------------
// grid (64, 16), block 256 (8 warps). 128 keys/block, 16 keys/warp, 2 keys in flight.
__global__ void scores_kernel(const float* __restrict__ cache_k) {
    const int b    = blockIdx.y;
    const int tid  = threadIdx.x;
    const int warp = tid >> 5;
    const int lane = tid & 31;

    __shared__ float4 qs[D4];   // 4 KB
    const float4* q4 = (const float4*)g_q + b * D4;
    for (int i = tid; i < D4; i += 256) qs[i] = q4[i];
    __syncthreads();

    const float4* K4 = (const float4*)cache_k;
    const int key_warp0 = blockIdx.x * 128 + warp * 16;

#pragma unroll 1
    for (int j = 0; j < 8; j++) {
        const int keyA = key_warp0 + j;
        const int keyB = keyA + 8;
        const float4* rowA = K4 + (size_t)(b * KV + keyA) * D4;
        const float4* rowB = K4 + (size_t)(b * KV + keyB) * D4;
        float accA = 0.f, accB = 0.f;
#pragma unroll
        for (int ii = 0; ii < 8; ii++) {
            const int i = lane + ii * 32;
            const float4 qq = qs[i];
            const float4 ka = rowA[i];
            const float4 kb = rowB[i];
            accA += ka.x * qq.x + ka.y * qq.y + ka.z * qq.z + ka.w * qq.w;
            accB += kb.x * qq.x + kb.y * qq.y + kb.z * qq.z + kb.w * qq.w;
        }
#pragma unroll
        for (int o = 16; o > 0; o >>= 1) {
            accA += __shfl_xor_sync(0xffffffffu, accA, o);
            accB += __shfl_xor_sync(0xffffffffu, accB, o);
        }
        if (lane == 0) {
            g_scores[b * SS + keyA] = accA * 0.03125f;   // 1/sqrt(1024)
            g_scores[b * SS + keyB] = accB * 0.03125f;
        }
    }
}

// ---------------- K2: appended-key score + softmax (weights in place) ----------------
// grid 16, block 256.
__global__ void softmax_kernel() {
    const int b   = blockIdx.x;
    const int tid = threadIdx.x;
    __shared__ float red[256];
    float* sc = g_scores + b * SS;

    // score for the new (appended) key
    float p = 0.f;
    for (int i = tid; i < D; i += 256) p += g_q[b * D + i] * g_nk[b * D + i];
    red[tid] = p; __syncthreads();
    for (int s = 128; s > 0; s >>= 1) {
        if (tid < s) red[tid] += red[tid + s];
        __syncthreads();
    }
    if (tid == 0) sc[KV] = red[0] * 0.03125f;
    __syncthreads();

    // max over KV+1 scores
    float m = -1e30f;
    for (int i = tid; i <= KV; i += 256) m = fmaxf(m, sc[i]);
    red[tid] = m; __syncthreads();
    for (int s = 128; s > 0; s >>= 1) {
        if (tid < s) red[tid] = fmaxf(red[tid], red[tid + s]);
        __syncthreads();
    }
    m = red[0];
    __syncthreads();

    // exp in place + sum
    float sum = 0.f;
    for (int i = tid; i <= KV; i += 256) {
        const float e = __expf(sc[i] - m);
        sc[i] = e;
        sum += e;
    }
    red[tid] = sum; __syncthreads();
    for (int s = 128; s > 0; s >>= 1) {
        if (tid < s) red[tid] += red[tid + s];
        __syncthreads();
    }
    const float inv = 1.f / red[0];
    __syncthreads();

    // normalize in place -> attention weights
    for (int i = tid; i <= KV; i += 256)
        sc[i] *= inv;
}

// ---------------- K3: partial out = sum_k w[k] * v[k][:] ----------------
// grid (NSPLIT, 16), block 256. One block covers the full D row for 128 keys.
__global__ void av_kernel(const float* __restrict__ cache_v) {
    const int split = blockIdx.x;      // 0..NSPLIT-1
    const int b     = blockIdx.y;
    const int tid   = threadIdx.x;     // 0..255
    const int keys_per = KV / NSPLIT;  // 128

    __shared__ float ws[KV / NSPLIT];
    const int key0 = split * keys_per;
    for (int i = tid; i < keys_per; i += 256)
        ws[i] = g_scores[b * SS + key0 + i];
    __syncthreads();

    const float4* V4 = (const float4*)cache_v;
    const float4* base = V4 + (size_t)(b * KV + key0) * D4 + tid;

    float4 acc = make_float4(0.f, 0.f, 0.f, 0.f);
#pragma unroll 8
    for (int k = 0; k < keys_per; k++) {
        const float  w = ws[k];
        const float4 v = base[(size_t)k * D4];
        acc.x += w * v.x; acc.y += w * v.y;
        acc.z += w * v.z; acc.w += w * v.w;
    }
    ((float4*)g_partial)[(size_t)(b * NSPLIT + split) * D4 + tid] = acc;
}

// ---------------- K4: combine splits + new-v term, round(.,4), write out ----------------
// grid (4, 16), block 64. Each thread owns one (b, float4-col).
__global__ void reduce_kernel(float* __restrict__ out) {
    const int b   = blockIdx.y;
    const int col = blockIdx.x * 64 + threadIdx.x;   // float4 column 0..255
    const float4* P4 = (const float4*)g_partial;

    float4 acc = make_float4(0.f, 0.f, 0.f, 0.f);
#pragma unroll
    for (int s = 0; s < NSPLIT; s++) {
        const float4 p = P4[(size_t)(b * NSPLIT + s) * D4 + col];
        acc.x += p.x; acc.y += p.y; acc.z += p.z; acc.w += p.w;
    }
    const float wn = g_scores[b * SS + KV];
    const float4 nv = ((const float4*)g_nv)[b * D4 + col];
    acc.x += wn * nv.x; acc.y += wn * nv.y;
    acc.z += wn * nv.z; acc.w += wn * nv.w;

    acc.x = rintf(acc.x * 10000.f) / 10000.f;
    acc.y = rintf(acc.y * 10000.f) / 10000.f;
    acc.z = rintf(acc.z * 10000.f) / 10000.f;
    acc.w = rintf(acc.w * 10000.f) / 10000.f;
    ((float4*)out)[b * D4 + col] = acc;
}

// ---------------- launcher ----------------
extern "C" void kernel_launch(void* const* d_in, const int* in_sizes, int n_in,
                              void* d_out, int out_size) {
    const float* x  = (const float*)d_in[0];
    const float* ck = (const float*)d_in[1];
    const float* cv = (const float*)d_in[2];
    const float* wq = (const float*)d_in[3];
    const float* wk = (const float*)d_in[4];
    const float* wv = (const float*)d_in[5];
    float* out = (float*)d_out;

    proj_kernel   <<<dim3(384, 2), 256>>>(x, wq, wk, wv);
    scores_kernel <<<dim3(64, B),  256>>>(ck);
    softmax_kernel<<<B,            256>>>();
    av_kernel     <<<dim3(NSPLIT, B), 256>>>(cv);
    reduce_kernel <<<dim3(4, B),   64>>>(out);
}

// round 3
// speedup vs baseline: 1.0661x; 1.0661x over previous
#include <cuda_runtime.h>

#define B   16
#define KV  8192
#define D   1024
#define D4  256        // D / 4 (float4 per row)
#define NSPLIT 64      // KV splits
#define KPS (KV / NSPLIT)   // 128 keys per split

// ---------------- device scratch ----------------
__device__ float g_q [B * D];
__device__ float g_nk[B * D];
__device__ float g_nv[B * D];
__device__ float g_partial[B * NSPLIT * D];   // 4 MB, unnormalized V partials
__device__ float g_m[B * NSPLIT];             // local maxima
__device__ float g_l[B * NSPLIT];             // local exp-sums

// ---------------- K0: projections q/new_k/new_v = x @ W^T ----------------
__global__ void proj_kernel(const float* __restrict__ x,
                            const float* __restrict__ wq,
                            const float* __restrict__ wk,
                            const float* __restrict__ wv) {
    __shared__ float4 xs[8 * D4];   // 8 batches of x, 32 KB
    const int tid  = threadIdx.x;
    const int warp = tid >> 5;
    const int lane = tid & 31;
    const int grp  = blockIdx.y;

    const float4* x4 = (const float4*)x;
    for (int i = tid; i < 8 * D4; i += 256) xs[i] = x4[grp * 8 * D4 + i];
    __syncthreads();

    const int row = blockIdx.x * 8 + warp;   // 0..3071
    const int mat = row >> 10;
    const int e   = row & 1023;
    const float* W  = (mat == 0) ? wq  : (mat == 1) ? wk  : wv;
    float*      out = (mat == 0) ? g_q : (mat == 1) ? g_nk : g_nv;
    const float4* W4 = (const float4*)W;

    float acc[8];
#pragma unroll
    for (int b = 0; b < 8; b++) acc[b] = 0.f;
#pragma unroll
    for (int ii = 0; ii < 8; ii++) {
        const int i = lane + ii * 32;
        const float4 w4 = W4[e * D4 + i];
#pragma unroll
        for (int b = 0; b < 8; b++) {
            const float4 xv = xs[b * D4 + i];
            acc[b] += w4.x * xv.x + w4.y * xv.y + w4.z * xv.z + w4.w * xv.w;
        }
    }
#pragma unroll
    for (int b = 0; b < 8; b++) {
#pragma unroll
        for (int o = 16; o > 0; o >>= 1)
            acc[b] += __shfl_xor_sync(0xffffffffu, acc[b], o);
    }
    if (lane == 0) {
#pragma unroll
        for (int b = 0; b < 8; b++)
            out[(grp * 8 + b) * D + e] = acc[b];
    }
}

// ---------------- K1: fused scores + local softmax + weighted AV partial ----------------
// grid (NSPLIT, B), block 256 (8 warps). Each block: 128 keys of one batch.
__global__ void attn_kernel(const float* __restrict__ cache_k,
                            const float* __restrict__ cache_v) {
    const int split = blockIdx.x;
    const int b     = blockIdx.y;
    const int tid   = threadIdx.x;
    const int warp  = tid >> 5;
    const int lane  = tid & 31;
    const int key0  = split * KPS;

    __shared__ float4 qs[D4];       // 4 KB
    __shared__ float  ss[KPS];      // scores -> exp weights
    __shared__ float  wred[8];

    const float4* q4 = (const float4*)g_q + b * D4;
    for (int i = tid; i < D4; i += 256) qs[i] = q4[i];
    __syncthreads();

    // ---- phase 1: scores for 128 keys (16 per warp, 2-key ILP) ----
    const float4* K4 = (const float4*)cache_k;
    const int kw0 = warp * 16;
#pragma unroll 1
    for (int j = 0; j < 8; j++) {
        const int kA = kw0 + j;
        const int kB = kA + 8;
        const float4* rowA = K4 + (size_t)(b * KV + key0 + kA) * D4;
        const float4* rowB = K4 + (size_t)(b * KV + key0 + kB) * D4;
        float aA = 0.f, aB = 0.f;
#pragma unroll
        for (int ii = 0; ii < 8; ii++) {
            const int i = lane + ii * 32;
            const float4 qq = qs[i];
            const float4 ka = rowA[i];
            const float4 kb = rowB[i];
            aA += ka.x * qq.x + ka.y * qq.y + ka.z * qq.z + ka.w * qq.w;
            aB += kb.x * qq.x + kb.y * qq.y + kb.z * qq.z + kb.w * qq.w;
        }
#pragma unroll
        for (int o = 16; o > 0; o >>= 1) {
            aA += __shfl_xor_sync(0xffffffffu, aA, o);
            aB += __shfl_xor_sync(0xffffffffu, aB, o);
        }
        if (lane == 0) {
            ss[kA] = aA * 0.03125f;   // 1/sqrt(1024)
            ss[kB] = aB * 0.03125f;
        }
    }
    __syncthreads();

    // ---- local softmax stats: m = max, l = sum exp(s-m); exp stored in ss ----
    float mv = (tid < KPS) ? ss[tid] : -1e30f;
#pragma unroll
    for (int o = 16; o > 0; o >>= 1)
        mv = fmaxf(mv, __shfl_xor_sync(0xffffffffu, mv, o));
    if (lane == 0) wred[warp] = mv;
    __syncthreads();
    if (tid == 0) {
        float m = wred[0];
#pragma unroll
        for (int w = 1; w < 8; w++) m = fmaxf(m, wred[w]);
        wred[0] = m;
    }
    __syncthreads();
    const float m = wred[0];
    __syncthreads();

    float ev = 0.f;
    if (tid < KPS) {
        const float e = __expf(ss[tid] - m);
        ss[tid] = e;
        ev = e;
    }
#pragma unroll
    for (int o = 16; o > 0; o >>= 1)
        ev += __shfl_xor_sync(0xffffffffu, ev, o);
    if (lane == 0) wred[warp] = ev;
    __syncthreads();
    if (tid == 0) {
        float l = 0.f;
#pragma unroll
        for (int w = 0; w < 8; w++) l += wred[w];
        g_m[b * NSPLIT + split] = m;
        g_l[b * NSPLIT + split] = l;
    }
    __syncthreads();

    // ---- phase 2: partial = sum_k exp(s_k - m) * v[k][:] ----
    const float4* V4 = (const float4*)cache_v;
    const float4* base = V4 + (size_t)(b * KV + key0) * D4 + tid;
    float4 acc = make_float4(0.f, 0.f, 0.f, 0.f);
#pragma unroll 8
    for (int k = 0; k < KPS; k++) {
        const float  w = ss[k];
        const float4 v = base[(size_t)k * D4];
        acc.x += w * v.x; acc.y += w * v.y;
        acc.z += w * v.z; acc.w += w * v.w;
    }
    ((float4*)g_partial)[(size_t)(b * NSPLIT + split) * D4 + tid] = acc;
}

// ---------------- K2: global rescale + new-token term + round ----------------
// grid B, block 256.
__global__ void reduce_kernel(float* __restrict__ out) {
    const int b   = blockIdx.x;
    const int tid = threadIdx.x;
    __shared__ float red[256];
    __shared__ float sc[NSPLIT];
    __shared__ float s_wn;

    // new-key score: q . new_k / sqrt(D)
    const float4 qq = ((const float4*)g_q )[b * D4 + tid];
    const float4 kk = ((const float4*)g_nk)[b * D4 + tid];
    red[tid] = qq.x * kk.x + qq.y * kk.y + qq.z * kk.z + qq.w * kk.w;
    __syncthreads();
    for (int s = 128; s > 0; s >>= 1) {
        if (tid < s) red[tid] += red[tid + s];
        __syncthreads();
    }
    const float s_new = red[0] * 0.03125f;

    if (tid == 0) {
        float M = s_new;
#pragma unroll
        for (int s = 0; s < NSPLIT; s++) M = fmaxf(M, g_m[b * NSPLIT + s]);
        float L = __expf(s_new - M);
#pragma unroll
        for (int s = 0; s < NSPLIT; s++) {
            const float e = __expf(g_m[b * NSPLIT + s] - M);
            sc[s] = e;
            L += g_l[b * NSPLIT + s] * e;
        }
        const float inv = 1.f / L;
#pragma unroll
        for (int s = 0; s < NSPLIT; s++) sc[s] *= inv;
        s_wn = __expf(s_new - M) * inv;
    }
    __syncthreads();

    const float4* P4 = (const float4*)g_partial + (size_t)b * NSPLIT * D4;
    float4 acc = make_float4(0.f, 0.f, 0.f, 0.f);
#pragma unroll 8
    for (int s = 0; s < NSPLIT; s++) {
        const float  w = sc[s];
        const float4 p = P4[(size_t)s * D4 + tid];
        acc.x += w * p.x; acc.y += w * p.y;
        acc.z += w * p.z; acc.w += w * p.w;
    }
    const float wn = s_wn;
    const float4 nv = ((const float4*)g_nv)[b * D4 + tid];
    acc.x += wn * nv.x; acc.y += wn * nv.y;
    acc.z += wn * nv.z; acc.w += wn * nv.w;

    acc.x = rintf(acc.x * 10000.f) / 10000.f;
    acc.y = rintf(acc.y * 10000.f) / 10000.f;
    acc.z = rintf(acc.z * 10000.f) / 10000.f;
    acc.w = rintf(acc.w * 10000.f) / 10000.f;
    ((float4*)out)[b * D4 + tid] = acc;
}

// ---------------- launcher ----------------
extern "C" void kernel_launch(void* const* d_in, const int* in_sizes, int n_in,
                              void* d_out, int out_size) {
    const float* x  = (const float*)d_in[0];
    const float* ck = (const float*)d_in[1];
    const float* cv = (const float*)d_in[2];
    const float* wq = (const float*)d_in[3];
    const float* wk = (const float*)d_in[4];
    const float* wv = (const float*)d_in[5];
    float* out = (float*)d_out;

    proj_kernel  <<<dim3(384, 2), 256>>>(x, wq, wk, wv);
    attn_kernel  <<<dim3(NSPLIT, B), 256>>>(ck, cv);
    reduce_kernel<<<B, 256>>>(out);
}

// round 4
// speedup vs baseline: 1.1118x; 1.0428x over previous
#include <cuda_runtime.h>

#define B   16
#define KV  8192
#define D   1024
#define D4  256        // D / 4 (float4 per row)
#define NSPLIT 64      // KV splits
#define KPS (KV / NSPLIT)   // 128 keys per split

// ---------------- device scratch ----------------
__device__ float g_q [B * D];
__device__ float g_nk[B * D];
__device__ float g_nv[B * D];
__device__ float g_partial[B * NSPLIT * D];   // 4 MB, unnormalized V partials
__device__ float g_m[B * NSPLIT];             // local maxima
__device__ float g_l[B * NSPLIT];             // local exp-sums

// ---------------- K0: projections q/new_k/new_v = x @ W^T ----------------
// grid (192, 2), block 256 (8 warps). Each warp: 2 output rows x 8 batches.
// 16 independent 16B weight loads in flight per warp per round.
__global__ void proj_kernel(const float* __restrict__ x,
                            const float* __restrict__ wq,
                            const float* __restrict__ wk,
                            const float* __restrict__ wv) {
    __shared__ float4 xs[8 * D4];   // 8 batches of x, 32 KB
    const int tid  = threadIdx.x;
    const int warp = tid >> 5;
    const int lane = tid & 31;
    const int grp  = blockIdx.y;    // batch group (0 or 1)

    const float4* x4 = (const float4*)x;
    for (int i = tid; i < 8 * D4; i += 256) xs[i] = x4[grp * 8 * D4 + i];
    __syncthreads();

    const int rowA = blockIdx.x * 16 + warp * 2;   // 0..3070 (even)
    const int rowB = rowA + 1;
    const int matA = rowA >> 10, eA = rowA & 1023;
    const int matB = rowB >> 10, eB = rowB & 1023;
    const float* WA  = (matA == 0) ? wq  : (matA == 1) ? wk  : wv;
    const float* WB  = (matB == 0) ? wq  : (matB == 1) ? wk  : wv;
    float*      outA = (matA == 0) ? g_q : (matA == 1) ? g_nk : g_nv;
    float*      outB = (matB == 0) ? g_q : (matB == 1) ? g_nk : g_nv;
    const float4* WA4 = (const float4*)WA + (size_t)eA * D4;
    const float4* WB4 = (const float4*)WB + (size_t)eB * D4;

    float accA[8], accB[8];
#pragma unroll
    for (int b = 0; b < 8; b++) { accA[b] = 0.f; accB[b] = 0.f; }

#pragma unroll
    for (int ii = 0; ii < 8; ii++) {
        const int i = lane + ii * 32;
        const float4 wa = WA4[i];
        const float4 wb = WB4[i];
#pragma unroll
        for (int b = 0; b < 8; b++) {
            const float4 xv = xs[b * D4 + i];
            accA[b] += wa.x * xv.x + wa.y * xv.y + wa.z * xv.z + wa.w * xv.w;
            accB[b] += wb.x * xv.x + wb.y * xv.y + wb.z * xv.z + wb.w * xv.w;
        }
    }
#pragma unroll
    for (int b = 0; b < 8; b++) {
#pragma unroll
        for (int o = 16; o > 0; o >>= 1) {
            accA[b] += __shfl_xor_sync(0xffffffffu, accA[b], o);
            accB[b] += __shfl_xor_sync(0xffffffffu, accB[b], o);
        }
    }
    if (lane == 0) {
#pragma unroll
        for (int b = 0; b < 8; b++) {
            outA[(grp * 8 + b) * D + eA] = accA[b];
            outB[(grp * 8 + b) * D + eB] = accB[b];
        }
    }
}

// ---------------- K1: fused scores + local softmax + weighted AV partial ----------------
// grid (NSPLIT, B), block 256 (8 warps). Each block: 128 keys of one batch.
__global__ void attn_kernel(const float* __restrict__ cache_k,
                            const float* __restrict__ cache_v) {
    const int split = blockIdx.x;
    const int b     = blockIdx.y;
    const int tid   = threadIdx.x;
    const int warp  = tid >> 5;
    const int lane  = tid & 31;
    const int key0  = split * KPS;

    __shared__ float4 qs[D4];       // 4 KB
    __shared__ float  ss[KPS];      // scores -> exp weights
    __shared__ float  wred[8];

    const float4* q4 = (const float4*)g_q + b * D4;
    for (int i = tid; i < D4; i += 256) qs[i] = q4[i];
    __syncthreads();

    // ---- phase 1: scores for 128 keys (16 per warp, 2-key ILP) ----
    const float4* K4 = (const float4*)cache_k;
    const int kw0 = warp * 16;
#pragma unroll 1
    for (int j = 0; j < 8; j++) {
        const int kA = kw0 + j;
        const int kB = kA + 8;
        const float4* rowA = K4 + (size_t)(b * KV + key0 + kA) * D4;
        const float4* rowB = K4 + (size_t)(b * KV + key0 + kB) * D4;
        float aA = 0.f, aB = 0.f;
#pragma unroll
        for (int ii = 0; ii < 8; ii++) {
            const int i = lane + ii * 32;
            const float4 qq = qs[i];
            const float4 ka = rowA[i];
            const float4 kb = rowB[i];
            aA += ka.x * qq.x + ka.y * qq.y + ka.z * qq.z + ka.w * qq.w;
            aB += kb.x * qq.x + kb.y * qq.y + kb.z * qq.z + kb.w * qq.w;
        }
#pragma unroll
        for (int o = 16; o > 0; o >>= 1) {
            aA += __shfl_xor_sync(0xffffffffu, aA, o);
            aB += __shfl_xor_sync(0xffffffffu, aB, o);
        }
        if (lane == 0) {
            ss[kA] = aA * 0.03125f;   // 1/sqrt(1024)
            ss[kB] = aB * 0.03125f;
        }
    }
    __syncthreads();

    // ---- local softmax stats: m = max, l = sum exp(s-m); exp stored in ss ----
    float mv = (tid < KPS) ? ss[tid] : -1e30f;
#pragma unroll
    for (int o = 16; o > 0; o >>= 1)
        mv = fmaxf(mv, __shfl_xor_sync(0xffffffffu, mv, o));
    if (lane == 0) wred[warp] = mv;
    __syncthreads();
    if (tid == 0) {
        float m = wred[0];
#pragma unroll
        for (int w = 1; w < 8; w++) m = fmaxf(m, wred[w]);
        wred[0] = m;
    }
    __syncthreads();
    const float m = wred[0];
    __syncthreads();

    float ev = 0.f;
    if (tid < KPS) {
        const float e = __expf(ss[tid] - m);
        ss[tid] = e;
        ev = e;
    }
#pragma unroll
    for (int o = 16; o > 0; o >>= 1)
        ev += __shfl_xor_sync(0xffffffffu, ev, o);
    if (lane == 0) wred[warp] = ev;
    __syncthreads();
    if (tid == 0) {
        float l = 0.f;
#pragma unroll
        for (int w = 0; w < 8; w++) l += wred[w];
        g_m[b * NSPLIT + split] = m;
        g_l[b * NSPLIT + split] = l;
    }
    __syncthreads();

    // ---- phase 2: partial = sum_k exp(s_k - m) * v[k][:] ----
    const float4* V4 = (const float4*)cache_v;
    const float4* base = V4 + (size_t)(b * KV + key0) * D4 + tid;
    float4 acc = make_float4(0.f, 0.f, 0.f, 0.f);
#pragma unroll 8
    for (int k = 0; k < KPS; k++) {
        const float  w = ss[k];
        const float4 v = base[(size_t)k * D4];
        acc.x += w * v.x; acc.y += w * v.y;
        acc.z += w * v.z; acc.w += w * v.w;
    }
    ((float4*)g_partial)[(size_t)(b * NSPLIT + split) * D4 + tid] = acc;
}

// ---------------- K2: global rescale + new-token term + round ----------------
// grid (4, B), block 256. Block covers 64 float4 columns; thread quads split NSPLIT.
__global__ void reduce_kernel(float* __restrict__ out) {
    const int b    = blockIdx.y;
    const int tid  = threadIdx.x;
    const int quad = tid >> 6;                    // 0..3  (16 splits each)
    const int c    = tid & 63;                    // local column
    const int col  = blockIdx.x * 64 + c;         // float4 column 0..255

    __shared__ float  red[256];
    __shared__ float  sc[NSPLIT];
    __shared__ float  s_wn;
    __shared__ float4 part[4][64];

    // new-key score: q . new_k / sqrt(D)  (256 threads cover all 256 float4s)
    {
        const float4 qq = ((const float4*)g_q )[b * D4 + tid];
        const float4 kk = ((const float4*)g_nk)[b * D4 + tid];
        red[tid] = qq.x * kk.x + qq.y * kk.y + qq.z * kk.z + qq.w * kk.w;
    }
    __syncthreads();
    for (int s = 128; s > 0; s >>= 1) {
        if (tid < s) red[tid] += red[tid + s];
        __syncthreads();
    }
    const float s_new = red[0] * 0.03125f;

    if (tid == 0) {
        float M = s_new;
#pragma unroll
        for (int s = 0; s < NSPLIT; s++) M = fmaxf(M, g_m[b * NSPLIT + s]);
        float L = __expf(s_new - M);
#pragma unroll
        for (int s = 0; s < NSPLIT; s++) {
            const float e = __expf(g_m[b * NSPLIT + s] - M);
            sc[s] = e;
            L += g_l[b * NSPLIT + s] * e;
        }
        const float inv = 1.f / L;
#pragma unroll
        for (int s = 0; s < NSPLIT; s++) sc[s] *= inv;
        s_wn = __expf(s_new - M) * inv;
    }
    __syncthreads();

    // each quad sums 16 splits for its column
    const float4* P4 = (const float4*)g_partial + (size_t)b * NSPLIT * D4 + col;
    float4 acc = make_float4(0.f, 0.f, 0.f, 0.f);
#pragma unroll
    for (int j = 0; j < 16; j++) {
        const int s = quad * 16 + j;
        const float  w = sc[s];
        const float4 p = P4[(size_t)s * D4];
        acc.x += w * p.x; acc.y += w * p.y;
        acc.z += w * p.z; acc.w += w * p.w;
    }
    part[quad][c] = acc;
    __syncthreads();

    if (quad == 0) {
        float4 a = part[0][c], p1 = part[1][c], p2 = part[2][c], p3 = part[3][c];
        a.x += p1.x + p2.x + p3.x;
        a.y += p1.y + p2.y + p3.y;
        a.z += p1.z + p2.z + p3.z;
        a.w += p1.w + p2.w + p3.w;

        const float wn = s_wn;
        const float4 nv = ((const float4*)g_nv)[b * D4 + col];
        a.x += wn * nv.x; a.y += wn * nv.y;
        a.z += wn * nv.z; a.w += wn * nv.w;

        a.x = rintf(a.x * 10000.f) / 10000.f;
        a.y = rintf(a.y * 10000.f) / 10000.f;
        a.z = rintf(a.z * 10000.f) / 10000.f;
        a.w = rintf(a.w * 10000.f) / 10000.f;
        ((float4*)out)[b * D4 + col] = a;
    }
}

// ---------------- launcher ----------------
extern "C" void kernel_launch(void* const* d_in, const int* in_sizes, int n_in,
                              void* d_out, int out_size) {
    const float* x  = (const float*)d_in[0];
    const float* ck = (const float*)d_in[1];
    const float* cv = (const float*)d_in[2];
    const float* wq = (const float*)d_in[3];
    const float* wk = (const float*)d_in[4];
    const float* wv = (const float*)d_in[5];
    float* out = (float*)d_out;

    proj_kernel  <<<dim3(192, 2), 256>>>(x, wq, wk, wv);
    attn_kernel  <<<dim3(NSPLIT, B), 256>>>(ck, cv);
    reduce_kernel<<<dim3(4, B), 256>>>(out);
}